// round 3
// baseline (speedup 1.0000x reference)
#include <cuda_runtime.h>
#include <math.h>

typedef double2 cplx;

#define DRED 32          // reduced Hilbert dim: {S1,S2} x 16 vib
#define DD   1024        // DRED^2, superoperator dim
#define AROWS 2048       // 2 functionals x up to 1024 time points

// -------- static device scratch (no allocations allowed) --------
static __device__ double d_H[DRED * DRED];
static __device__ double d_gval[1];
static __device__ cplx d_P [DD * DD];   // scaled generator M / 2^8
static __device__ cplx d_E [DD * DD];   // expm accumulator / U powers
static __device__ cplx d_T [DD * DD];   // Taylor term ping
static __device__ cplx d_T2[DD * DD];   // Taylor term pong
static __device__ cplx d_A [AROWS * DD];// stacked rows w_c U^t

// ---------------- model construction ----------------
__device__ __forceinline__ double qmat(int r, int c) {
    // (a + a^dag)/sqrt(2) for a 4-level oscillator
    if (c == r + 1) return sqrt((double)c * 0.5);
    if (r == c + 1) return sqrt((double)r * 0.5);
    return 0.0;
}

__global__ void k_build_H(const float* log_g) {
    int a = threadIdx.x;                     // 0..1023 -> (i,j) of 32x32
    if (a == 0) d_gval[0] = (double)expf(log_g[0]);  // matches f32 exp then f64 cast
    int i = a >> 5, j = a & 31;
    int si = i >> 4, vi = i & 15, v6i = vi >> 2, v10i = vi & 3;
    int sj = j >> 4, vj = j & 15, v6j = vj >> 2, v10j = vj & 3;
    const double CM2EV = 0.00012398419;
    const double E_S1 = 3.995, E_S2 = 4.9183;
    const double om6a = 596.0 * CM2EV, om10a = 919.0 * CM2EV;
    const double kap1 = -0.0964, kap2 = 0.1193;
    const double lam = 0.1825, gam = -0.018;
    double val = 0.0;
    if (si == sj) {
        if (vi == vj) val += (si == 0 ? E_S1 : E_S2) + om6a * v6i + om10a * v10i;
        if (v10i == v10j) val += (si == 0 ? kap1 : kap2) * qmat(v6i, v6j);
    } else {
        if (v6i == v6j) {
            double q2 = 0.0;
            #pragma unroll
            for (int m = 0; m < 4; m++) q2 += qmat(v10i, m) * qmat(m, v10j);
            val += lam * qmat(v10i, v10j) + gam * q2;
        }
    }
    d_H[i * DRED + j] = val;
}

// Build P = (Lc + g*Ld0) * (DT/HBAR) / 2^8 on the reduced space.
// Row-major vec convention: index (i,j) -> i*32+j, kron(A,B)[(i,j),(k,l)] = A[i,k]B[j,l].
// Lc entry = -i( dik*H[j,l] - H[i,k]*djl )   (H real symmetric)
// Ld0 entry = Lj[i,k]Lj[j,l] - 0.5 dik*LdL[j,l] - 0.5 LdL[i,k]*djl
//   Lj[a,b] = (a<16 && b==a+16);  LdL[a,b] = (a==b && a>=16)
__global__ void k_build_P() {
    int idx = blockIdx.x * blockDim.x + threadIdx.x;  // 0 .. DD*DD-1
    int r = idx >> 10, c = idx & 1023;
    int i = r >> 5, j = r & 31;
    int k = c >> 5, l = c & 31;
    const double scale = (1.0 / 0.6582119569) / 256.0;
    double g = d_gval[0];
    double lik = (i < 16 && k == i + 16) ? 1.0 : 0.0;
    double ljl = (j < 16 && l == j + 16) ? 1.0 : 0.0;
    double dterm = lik * ljl;
    if (i == k && j == l) {
        if (j >= 16) dterm -= 0.5;
        if (i >= 16) dterm -= 0.5;
    }
    double re = g * dterm * scale;
    double im = 0.0;
    if (i == k) im -= d_H[j * DRED + l];
    if (j == l) im += d_H[i * DRED + k];
    im *= scale;
    d_P[idx] = make_double2(re, im);
}

__global__ void k_init_E() {
    int idx = blockIdx.x * blockDim.x + threadIdx.x;
    int r = idx >> 10, c = idx & 1023;
    cplx p = d_P[idx];
    d_T[idx] = p;
    if (r == c) p.x += 1.0;
    d_E[idx] = p;
}

__global__ void k_add(cplx* __restrict__ dst, const cplx* __restrict__ src) {
    int idx = blockIdx.x * blockDim.x + threadIdx.x;
    cplx a = dst[idx], b = src[idx];
    a.x += b.x; a.y += b.y;
    dst[idx] = a;
}

// rows 0,1 of A: w1 = diag indicator over S1 block, w2 = over S2 block
__global__ void k_Ainit(cplx* __restrict__ A) {
    int idx = blockIdx.x * blockDim.x + threadIdx.x;  // 0..2047
    if (idx >= 2 * DD) return;
    int r = idx >> 10, c = idx & 1023;
    double v = 0.0;
    if (c % 33 == 0) {  // diagonal entries (i*32+i = 33*i)
        if (r == 0 && c < 528) v = 1.0;            // i in [0,16)  -> S1
        if (r == 1 && c >= 528) v = 1.0;           // i in [16,32) -> S2
    }
    A[idx] = make_double2(v, 0.0);
}

__global__ void k_extract(const cplx* __restrict__ A, float* __restrict__ out, int n) {
    int t = blockIdx.x * blockDim.x + threadIdx.x;
    if (t >= n) return;
    out[t] = 0.0f;                                             // ground pop = exactly 0
    out[n + t]     = (float)A[(size_t)(2 * t) * DD + 528].x;   // S1
    out[2 * n + t] = (float)A[(size_t)(2 * t + 1) * DD + 528].x; // S2
}

// ---------------- complex double GEMM: C = alpha * A(MxK) @ B(KxN), N=K=DD ----------------
#define BM 64
#define BN 64
#define BK 8
#define TM 4
#define TN 4

__global__ void __launch_bounds__(256) zgemm(
    int M, double alpha,
    const cplx* __restrict__ A, const cplx* __restrict__ B, cplx* __restrict__ C)
{
    __shared__ cplx sA[BM][BK];
    __shared__ cplx sB[BK][BN];

    int bx = blockIdx.x;             // N tile (16 tiles)
    int by = blockIdx.y;             // M tile
    int tid = threadIdx.x;
    int tx = tid & 15, ty = tid >> 4;
    int row0 = by * BM + ty * TM;
    int col0 = bx * BN + tx * TN;

    double accx[TM][TN] = {{0.0}}, accy[TM][TN] = {{0.0}};

    for (int kt = 0; kt < DD; kt += BK) {
        #pragma unroll
        for (int u = 0; u < 2; u++) {
            int e = tid + u * 256;           // 0..511
            int am = e >> 3, ak = e & 7;
            int gr = by * BM + am;
            sA[am][ak] = (gr < M) ? A[(size_t)gr * DD + kt + ak]
                                  : make_double2(0.0, 0.0);
        }
        #pragma unroll
        for (int u = 0; u < 2; u++) {
            int e = tid + u * 256;
            int bk = e >> 6, bn = e & 63;
            sB[bk][bn] = B[(size_t)(kt + bk) * DD + bx * BN + bn];
        }
        __syncthreads();

        #pragma unroll
        for (int kk = 0; kk < BK; kk++) {
            cplx a[TM], b[TN];
            #pragma unroll
            for (int i = 0; i < TM; i++) a[i] = sA[ty * TM + i][kk];
            #pragma unroll
            for (int j = 0; j < TN; j++) b[j] = sB[kk][tx * TN + j];
            #pragma unroll
            for (int i = 0; i < TM; i++)
                #pragma unroll
                for (int j = 0; j < TN; j++) {
                    accx[i][j] = fma(a[i].x,  b[j].x, accx[i][j]);
                    accx[i][j] = fma(-a[i].y, b[j].y, accx[i][j]);
                    accy[i][j] = fma(a[i].x,  b[j].y, accy[i][j]);
                    accy[i][j] = fma(a[i].y,  b[j].x, accy[i][j]);
                }
        }
        __syncthreads();
    }

    #pragma unroll
    for (int i = 0; i < TM; i++) {
        int r = row0 + i;
        if (r < M) {
            #pragma unroll
            for (int j = 0; j < TN; j++)
                C[(size_t)r * DD + col0 + j] =
                    make_double2(alpha * accx[i][j], alpha * accy[i][j]);
        }
    }
}

// ---------------- driver ----------------
extern "C" void kernel_launch(void* const* d_in, const int* in_sizes, int n_in,
                              void* d_out, int out_size) {
    const float* log_g = (const float*)d_in[0];
    int n_steps = out_size / 3;                 // 1000
    if (n_steps < 1) n_steps = 1;
    if (n_steps > 1024) n_steps = 1024;         // AROWS bound

    void *pP, *pE, *pT, *pT2, *pA;
    cudaGetSymbolAddress(&pP, d_P);
    cudaGetSymbolAddress(&pE, d_E);
    cudaGetSymbolAddress(&pT, d_T);
    cudaGetSymbolAddress(&pT2, d_T2);
    cudaGetSymbolAddress(&pA, d_A);

    // Phase 0: build generator
    k_build_H<<<1, 1024>>>(log_g);
    k_build_P<<<DD, 1024>>>();
    k_init_E<<<DD, 1024>>>();

    // Phase 1: Taylor series, E = sum_{k=0..10} P^k/k!  (||P||_1 ~ 0.074)
    cplx* Tc = (cplx*)pT;
    cplx* Tn = (cplx*)pT2;
    for (int k = 2; k <= 10; k++) {
        zgemm<<<dim3(16, 16), 256>>>(DD, 1.0 / (double)k, Tc, (cplx*)pP, Tn);
        k_add<<<DD, 1024>>>((cplx*)pE, Tn);
        cplx* tmp = Tc; Tc = Tn; Tn = tmp;
    }

    // Phase 2: 8 squarings -> U = expm((Lc + g Ld0)*DT/HBAR)
    cplx* Ec = (cplx*)pE;
    cplx* Eo = (cplx*)pP;   // P no longer needed
    for (int t = 0; t < 8; t++) {
        zgemm<<<dim3(16, 16), 256>>>(DD, 1.0, Ec, Ec, Eo);
        cplx* tmp = Ec; Ec = Eo; Eo = tmp;
    }
    // Ec holds U

    // Phase 3: time doubling. A rows [2t+c] = w_c U^t
    cplx* Acat = (cplx*)pA;
    k_Ainit<<<8, 256>>>(Acat);

    cplx* Bc = Ec;
    cplx* Bn = (Tc != Ec && Tc != Eo) ? Tc : Tn;  // a free 16MB buffer
    // (pT/pT2 are both free here; pick one that can't alias Ec)
    if (Bn == Bc) Bn = (cplx*)pT2;

    int nd = 0;
    while ((1 << nd) < n_steps) nd++;
    if (nd > 10) nd = 10;

    int rows = 2;
    for (int kd = 0; kd < nd; kd++) {
        zgemm<<<dim3(16, (rows + BM - 1) / BM), 256>>>(
            rows, 1.0, Acat, Bc, Acat + (size_t)rows * DD);
        rows <<= 1;
        if (kd < nd - 1) {
            zgemm<<<dim3(16, 16), 256>>>(DD, 1.0, Bc, Bc, Bn);
            cplx* tmp = Bc; Bc = Bn; Bn = tmp;
        }
    }

    // Phase 4: extract pops
    k_extract<<<(n_steps + 255) / 256, 256>>>(Acat, (float*)d_out, n_steps);
}

// round 4
// speedup vs baseline: 98.3528x; 98.3528x over previous
#include <cuda_runtime.h>
#include <math.h>

#define DD 1024

// ---------------- static device storage (no allocation allowed) ----------------
static __device__ double d_H[32 * 32];
static __device__ double d_g;
static __device__ double d_CS[DD * DD];     // symmetric part of G(B_n), column-major by n
static __device__ double d_CA[DD * DD];     // antisymmetric part
static __device__ float  d_M0[DD * DD];     // P (scaled generator), later scratch
static __device__ float  d_M1[DD * DD];     // P^2, later scratch
static __device__ float  d_M2[DD * DD];     // P^3
static __device__ float  d_M3[DD * DD];     // X / E / U
static __device__ float  d_M4[DD * DD];     // T / scratch
static __device__ float  d_Arows[2048 * DD];// stacked rows w_c U^a

// ---------------- model: H on reduced 32-dim space ({S1,S2} x 16 vib) ----------------
__device__ __forceinline__ double qmat(int r, int c) {
    if (c == r + 1) return sqrt((double)c * 0.5);
    if (r == c + 1) return sqrt((double)r * 0.5);
    return 0.0;
}

__global__ void k_build_H(const float* log_g) {
    int a = threadIdx.x;                       // 0..1023 -> (i,j)
    if (a == 0) d_g = (double)expf(log_g[0]);  // f32 exp then cast (matches reference)
    int i = a >> 5, j = a & 31;
    int si = i >> 4, vi = i & 15, v6i = vi >> 2, v10i = vi & 3;
    int sj = j >> 4, vj = j & 15, v6j = vj >> 2, v10j = vj & 3;
    const double CM2EV = 0.00012398419;
    const double E_S1 = 3.995, E_S2 = 4.9183;
    const double om6a = 596.0 * CM2EV, om10a = 919.0 * CM2EV;
    const double kap1 = -0.0964, kap2 = 0.1193;
    const double lam = 0.1825, gam = -0.018;
    double val = 0.0;
    if (si == sj) {
        if (vi == vj) val += (si == 0 ? E_S1 : E_S2) + om6a * v6i + om10a * v10i;
        if (v10i == v10j) val += (si == 0 ? kap1 : kap2) * qmat(v6i, v6j);
    } else {
        if (v6i == v6j) {
            double q2 = 0.0;
            #pragma unroll
            for (int m = 0; m < 4; m++) q2 += qmat(v10i, m) * qmat(m, v10j);
            val += lam * qmat(v10i, v10j) + gam * q2;
        }
    }
    d_H[i * 32 + j] = val;
}

// ---------------- real hermitian basis bookkeeping ----------------
// m in [0,32): diag E_mm
// m in [32,528): S-pair (i<j): (E_ij + E_ji)/sqrt2
// m in [528,1024): A-pair (i<j): i(E_ij - E_ji)/sqrt2
__device__ __forceinline__ void decode_basis(int m, int& type, int& p, int& q) {
    if (m < 32) { type = 0; p = q = m; return; }
    int pi = (m < 528) ? (m - 32) : (m - 528);
    type = (m < 528) ? 1 : 2;
    int r = 0, cnt = 31;
    while (pi >= cnt) { pi -= cnt; r++; cnt--; }
    p = r; q = r + 1 + pi;
}

// Stage: for column n, compute C = G(B_n) in hermitian decomposition C = CS + i*CA.
// G(rho) = -i(rho H - H rho) + g( Lj rho Lj^T - 1/2 rho L - 1/2 L rho )
// with H real sym, Lj[a,b] = (a<16 && b==a+16), L = diag(a>=16).
// For rho = S (real sym):   A-part = H S - S H;  S-part = g*diss(S)
// For rho = i A (A antisym): S-part = A H - H A;  A-part = g*diss(A)
__global__ void k_stageG() {
    int n = blockIdx.x;
    int ab = threadIdx.x;
    int a = ab >> 5, b = ab & 31;
    int type, p, q;
    decode_basis(n, type, p, q);
    double v = (type == 0) ? 1.0 : 0.70710678118654752440;
    // nonzeros of the real matrix X (= S_n or A_n): (c0,d0,w0), (c1,d1,w1)
    int nc = (type == 0) ? 1 : 2;
    int cc[2] = { p, q };
    int dd[2] = { q, p };
    double ww[2] = { v, (type == 2) ? -v : v };

    const double g = d_g;
    double HX = 0.0, XH = 0.0, Xab = 0.0, X16 = 0.0;
    for (int e = 0; e < nc; e++) {
        if (dd[e] == b) HX += d_H[a * 32 + cc[e]] * ww[e];       // (H X)[a,b]
        if (cc[e] == a) XH += ww[e] * d_H[dd[e] * 32 + b];       // (X H)[a,b]
        if (cc[e] == a && dd[e] == b) Xab += ww[e];
        if (a < 16 && b < 16 && cc[e] == a + 16 && dd[e] == b + 16) X16 += ww[e];
    }
    double diss = g * (X16 - 0.5 * Xab * (double)((a >= 16) + (b >= 16)));
    double cs, ca;
    if (type == 2) { cs = XH - HX; ca = diss; }   // input iA: S' = A H - H A
    else           { ca = HX - XH; cs = diss; }   // input S:  A' = H S - S H
    d_CS[n * DD + ab] = cs;
    d_CA[n * DD + ab] = ca;
}

// Project columns onto the basis and scale: P[m,n] = <B_m, G(B_n)> * (DT/HBAR)/2^8
__global__ void k_project() {
    int idx = blockIdx.x * 1024 + threadIdx.x;
    int m = idx >> 10, n = idx & 1023;
    int type, i, j;
    decode_basis(m, type, i, j);
    const double SQ2 = 1.41421356237309504880;
    double val;
    if (type == 0)      val = d_CS[n * DD + i * 33];
    else if (type == 1) val = SQ2 * d_CS[n * DD + i * 32 + j];
    else                val = SQ2 * d_CA[n * DD + i * 32 + j];
    const double scale = (1.0 / 0.6582119569) / 256.0;
    d_M0[m * DD + n] = (float)(val * scale);
}

// ---------------- elementwise Taylor assembly (Paterson-Stockmeyer, order 6) ----------------
// X = (1/6) I + (1/24) P + (1/120) P2 + (1/720) P3   -> M3
__global__ void k_combineX() {
    int idx = blockIdx.x * 1024 + threadIdx.x;
    int r = idx >> 10, c = idx & 1023;
    float x = (1.0f/24.0f) * d_M0[idx] + (1.0f/120.0f) * d_M1[idx] + (1.0f/720.0f) * d_M2[idx];
    if (r == c) x += 1.0f/6.0f;
    d_M3[idx] = x;
}
// E = I + P + P2/2 + T  -> M3   (T = P3 @ X in M4)
__global__ void k_finishE() {
    int idx = blockIdx.x * 1024 + threadIdx.x;
    int r = idx >> 10, c = idx & 1023;
    float x = d_M0[idx] + 0.5f * d_M1[idx] + d_M4[idx];
    if (r == c) x += 1.0f;
    d_M3[idx] = x;
}

// rows 0,1 of Arows: w1 = sum of diag coeffs 0..15 (S1), w2 = 16..31 (S2)
__global__ void k_Ainit() {
    int r = blockIdx.x, c = threadIdx.x;
    float v = 0.0f;
    if (r == 0 && c < 16) v = 1.0f;
    if (r == 1 && c >= 16 && c < 32) v = 1.0f;
    d_Arows[r * DD + c] = v;
}

__global__ void k_extract(float* __restrict__ out, int n) {
    int t = blockIdx.x * blockDim.x + threadIdx.x;
    if (t >= n) return;
    out[t] = 0.0f;                                    // ground state pop: exactly 0
    out[n + t]     = d_Arows[(size_t)(2 * t) * DD + 16];
    out[2 * n + t] = d_Arows[(size_t)(2 * t + 1) * DD + 16];
}

// ---------------- fp32 GEMM: C(MxDD) = A(MxDD) @ B(DDxDD) ----------------
// 64x64 tiles, 64 threads, 8x8 per thread, BK=16.
#define GBK 16
__global__ void __launch_bounds__(64) sgemm64(
    int M, const float* __restrict__ A, const float* __restrict__ B, float* __restrict__ C)
{
    __shared__ float sA[GBK][64];   // transposed A tile
    __shared__ float sB[GBK][64];
    int bx = blockIdx.x, by = blockIdx.y;
    int t = threadIdx.x;
    int tx = t & 7, ty = t >> 3;
    int row0 = by * 64;

    float acc[8][8];
    #pragma unroll
    for (int i = 0; i < 8; i++)
        #pragma unroll
        for (int j = 0; j < 8; j++) acc[i][j] = 0.0f;

    for (int kt = 0; kt < DD; kt += GBK) {
        #pragma unroll
        for (int u = 0; u < 4; u++) {
            int e = t + 64 * u;          // 0..255
            int r = e >> 2, kc = e & 3;
            float4 va = make_float4(0.f, 0.f, 0.f, 0.f);
            if (row0 + r < M)
                va = *(const float4*)&A[(size_t)(row0 + r) * DD + kt + kc * 4];
            sA[kc * 4 + 0][r] = va.x;
            sA[kc * 4 + 1][r] = va.y;
            sA[kc * 4 + 2][r] = va.z;
            sA[kc * 4 + 3][r] = va.w;
        }
        #pragma unroll
        for (int u = 0; u < 4; u++) {
            int e = t + 64 * u;
            int k = e >> 4, nc2 = e & 15;
            *(float4*)&sB[k][nc2 * 4] =
                *(const float4*)&B[(size_t)(kt + k) * DD + bx * 64 + nc2 * 4];
        }
        __syncthreads();
        #pragma unroll
        for (int kk = 0; kk < GBK; kk++) {
            float a[8], b[8];
            *(float4*)&a[0] = *(float4*)&sA[kk][ty * 8];
            *(float4*)&a[4] = *(float4*)&sA[kk][ty * 8 + 4];
            *(float4*)&b[0] = *(float4*)&sB[kk][tx * 8];
            *(float4*)&b[4] = *(float4*)&sB[kk][tx * 8 + 4];
            #pragma unroll
            for (int i = 0; i < 8; i++)
                #pragma unroll
                for (int j = 0; j < 8; j++)
                    acc[i][j] = fmaf(a[i], b[j], acc[i][j]);
        }
        __syncthreads();
    }
    #pragma unroll
    for (int i = 0; i < 8; i++) {
        int r = row0 + ty * 8 + i;
        if (r < M) {
            float4 o0 = make_float4(acc[i][0], acc[i][1], acc[i][2], acc[i][3]);
            float4 o1 = make_float4(acc[i][4], acc[i][5], acc[i][6], acc[i][7]);
            *(float4*)&C[(size_t)r * DD + bx * 64 + tx * 8]     = o0;
            *(float4*)&C[(size_t)r * DD + bx * 64 + tx * 8 + 4] = o1;
        }
    }
}

// skinny GEMM for tiny M (2..32): C(MxDD) = A(MxDD) @ B(DDxDD); 64 threads, 16 blocks
template <int MM>
__global__ void __launch_bounds__(64) sgemm_sk(
    const float* __restrict__ A, const float* __restrict__ B, float* __restrict__ C)
{
    __shared__ float sA[MM * 64];
    int c = blockIdx.x * 64 + threadIdx.x;
    float acc[MM];
    #pragma unroll
    for (int r = 0; r < MM; r++) acc[r] = 0.0f;
    for (int kt = 0; kt < DD; kt += 64) {
        for (int e = threadIdx.x; e < MM * 64; e += 64) {
            int r = e >> 6, kk = e & 63;
            sA[e] = A[(size_t)r * DD + kt + kk];
        }
        __syncthreads();
        #pragma unroll 8
        for (int kk = 0; kk < 64; kk++) {
            float bv = B[(size_t)(kt + kk) * DD + c];
            #pragma unroll
            for (int r = 0; r < MM; r++)
                acc[r] = fmaf(sA[r * 64 + kk], bv, acc[r]);
        }
        __syncthreads();
    }
    #pragma unroll
    for (int r = 0; r < MM; r++) C[(size_t)r * DD + c] = acc[r];
}

// ---------------- driver ----------------
extern "C" void kernel_launch(void* const* d_in, const int* in_sizes, int n_in,
                              void* d_out, int out_size) {
    const float* log_g = (const float*)d_in[0];
    int n_steps = out_size / 3;
    if (n_steps < 1) n_steps = 1;
    if (n_steps > 1024) n_steps = 1024;

    void *p0, *p1, *p2, *p3, *p4, *pA;
    cudaGetSymbolAddress(&p0, d_M0);
    cudaGetSymbolAddress(&p1, d_M1);
    cudaGetSymbolAddress(&p2, d_M2);
    cudaGetSymbolAddress(&p3, d_M3);
    cudaGetSymbolAddress(&p4, d_M4);
    cudaGetSymbolAddress(&pA, d_Arows);
    float *M0 = (float*)p0, *M1 = (float*)p1, *M2 = (float*)p2,
          *M3 = (float*)p3, *M4 = (float*)p4, *Ar = (float*)pA;

    // Phase 0: build generator P (real basis, fp32) in M0
    k_build_H<<<1, 1024>>>(log_g);
    k_stageG<<<1024, 1024>>>();
    k_project<<<1024, 1024>>>();

    dim3 gfull(16, 16);
    // Phase 1: expm via order-6 Taylor (Paterson-Stockmeyer) + 8 squarings
    sgemm64<<<gfull, 64>>>(DD, M0, M0, M1);   // P2
    sgemm64<<<gfull, 64>>>(DD, M1, M0, M2);   // P3
    k_combineX<<<1024, 1024>>>();             // M3 = X
    sgemm64<<<gfull, 64>>>(DD, M2, M3, M4);   // T = P3 @ X
    k_finishE<<<1024, 1024>>>();              // M3 = E
    float* Ec = M3; float* Eo = M4;
    for (int s = 0; s < 8; s++) {
        sgemm64<<<gfull, 64>>>(DD, Ec, Ec, Eo);
        float* tmp = Ec; Ec = Eo; Eo = tmp;
    }
    // Ec == M3 holds U

    // Phase 2: time doubling. Arows[2a+c] = w_c U^a.
    k_Ainit<<<2, 1024>>>();
    float* Bc = Ec;                 // U
    float* scratchA = M0, *scratchB = M1;  // P, P2 dead
    int nd = 0;
    while ((1 << nd) < n_steps) nd++;
    if (nd > 10) nd = 10;
    int rows = 2;
    for (int kd = 0; kd < nd; kd++) {
        float* Adst = Ar + (size_t)rows * DD;
        switch (rows) {
            case 2:  sgemm_sk<2> <<<16, 64>>>(Ar, Bc, Adst); break;
            case 4:  sgemm_sk<4> <<<16, 64>>>(Ar, Bc, Adst); break;
            case 8:  sgemm_sk<8> <<<16, 64>>>(Ar, Bc, Adst); break;
            case 16: sgemm_sk<16><<<16, 64>>>(Ar, Bc, Adst); break;
            case 32: sgemm_sk<32><<<16, 64>>>(Ar, Bc, Adst); break;
            default:
                sgemm64<<<dim3(16, rows / 64), 64>>>(rows, Ar, Bc, Adst);
        }
        rows <<= 1;
        if (kd < nd - 1) {
            float* Bn = (Bc == scratchA) ? scratchB : scratchA;
            sgemm64<<<gfull, 64>>>(DD, Bc, Bc, Bn);
            Bc = Bn;
        }
    }

    // Phase 3: extract populations
    k_extract<<<(n_steps + 255) / 256, 256>>>((float*)d_out, n_steps);
}

// round 5
// speedup vs baseline: 112.9302x; 1.1482x over previous
#include <cuda_runtime.h>
#include <math.h>

#define DD 1024

// ---------------- static device storage (no allocation allowed) ----------------
static __device__ double d_H[32 * 32];
static __device__ double d_g;
static __device__ double d_CS[DD * DD];     // symmetric part of G(B_n), column-major by n
static __device__ double d_CA[DD * DD];     // antisymmetric part
static __device__ float  d_M0[DD * DD];     // P (scaled generator), later scratch
static __device__ float  d_M1[DD * DD];     // P^2, later scratch
static __device__ float  d_M2[DD * DD];     // P^3
static __device__ float  d_M3[DD * DD];     // X / E / U
static __device__ float  d_M4[DD * DD];     // T / scratch
static __device__ float  d_Arows[2048 * DD];// stacked rows w_c U^a

// ---------------- model: H on reduced 32-dim space ({S1,S2} x 16 vib) ----------------
__device__ __forceinline__ double qmat(int r, int c) {
    if (c == r + 1) return sqrt((double)c * 0.5);
    if (r == c + 1) return sqrt((double)r * 0.5);
    return 0.0;
}

__global__ void k_build_H(const float* log_g) {
    int a = threadIdx.x;                       // 0..1023 -> (i,j)
    if (a == 0) d_g = (double)expf(log_g[0]);  // f32 exp then cast (matches reference)
    int i = a >> 5, j = a & 31;
    int si = i >> 4, vi = i & 15, v6i = vi >> 2, v10i = vi & 3;
    int sj = j >> 4, vj = j & 15, v6j = vj >> 2, v10j = vj & 3;
    const double CM2EV = 0.00012398419;
    const double E_S1 = 3.995, E_S2 = 4.9183;
    const double om6a = 596.0 * CM2EV, om10a = 919.0 * CM2EV;
    const double kap1 = -0.0964, kap2 = 0.1193;
    const double lam = 0.1825, gam = -0.018;
    double val = 0.0;
    if (si == sj) {
        if (vi == vj) val += (si == 0 ? E_S1 : E_S2) + om6a * v6i + om10a * v10i;
        if (v10i == v10j) val += (si == 0 ? kap1 : kap2) * qmat(v6i, v6j);
    } else {
        if (v6i == v6j) {
            double q2 = 0.0;
            #pragma unroll
            for (int m = 0; m < 4; m++) q2 += qmat(v10i, m) * qmat(m, v10j);
            val += lam * qmat(v10i, v10j) + gam * q2;
        }
    }
    d_H[i * 32 + j] = val;
}

// ---------------- real hermitian basis bookkeeping ----------------
// m in [0,32): diag E_mm
// m in [32,528): S-pair (i<j): (E_ij + E_ji)/sqrt2
// m in [528,1024): A-pair (i<j): i(E_ij - E_ji)/sqrt2
__device__ __forceinline__ void decode_basis(int m, int& type, int& p, int& q) {
    if (m < 32) { type = 0; p = q = m; return; }
    int pi = (m < 528) ? (m - 32) : (m - 528);
    type = (m < 528) ? 1 : 2;
    int r = 0, cnt = 31;
    while (pi >= cnt) { pi -= cnt; r++; cnt--; }
    p = r; q = r + 1 + pi;
}

// Stage: for column n, compute C = G(B_n) in hermitian decomposition C = CS + i*CA.
__global__ void k_stageG() {
    int n = blockIdx.x;
    int ab = threadIdx.x;
    int a = ab >> 5, b = ab & 31;
    int type, p, q;
    decode_basis(n, type, p, q);
    double v = (type == 0) ? 1.0 : 0.70710678118654752440;
    int nc = (type == 0) ? 1 : 2;
    int cc[2] = { p, q };
    int dd[2] = { q, p };
    double ww[2] = { v, (type == 2) ? -v : v };

    const double g = d_g;
    double HX = 0.0, XH = 0.0, Xab = 0.0, X16 = 0.0;
    for (int e = 0; e < nc; e++) {
        if (dd[e] == b) HX += d_H[a * 32 + cc[e]] * ww[e];
        if (cc[e] == a) XH += ww[e] * d_H[dd[e] * 32 + b];
        if (cc[e] == a && dd[e] == b) Xab += ww[e];
        if (a < 16 && b < 16 && cc[e] == a + 16 && dd[e] == b + 16) X16 += ww[e];
    }
    double diss = g * (X16 - 0.5 * Xab * (double)((a >= 16) + (b >= 16)));
    double cs, ca;
    if (type == 2) { cs = XH - HX; ca = diss; }
    else           { ca = HX - XH; cs = diss; }
    d_CS[n * DD + ab] = cs;
    d_CA[n * DD + ab] = ca;
}

// Project columns onto the basis and scale: P[m,n] = <B_m, G(B_n)> * (DT/HBAR)/2^8
__global__ void k_project() {
    int idx = blockIdx.x * 1024 + threadIdx.x;
    int m = idx >> 10, n = idx & 1023;
    int type, i, j;
    decode_basis(m, type, i, j);
    const double SQ2 = 1.41421356237309504880;
    double val;
    if (type == 0)      val = d_CS[n * DD + i * 33];
    else if (type == 1) val = SQ2 * d_CS[n * DD + i * 32 + j];
    else                val = SQ2 * d_CA[n * DD + i * 32 + j];
    const double scale = (1.0 / 0.6582119569) / 256.0;
    d_M0[m * DD + n] = (float)(val * scale);
}

// ---------------- elementwise Taylor assembly (Paterson-Stockmeyer, order 6) ----------------
__global__ void k_combineX() {
    int idx = blockIdx.x * 1024 + threadIdx.x;
    int r = idx >> 10, c = idx & 1023;
    float x = (1.0f/24.0f) * d_M0[idx] + (1.0f/120.0f) * d_M1[idx] + (1.0f/720.0f) * d_M2[idx];
    if (r == c) x += 1.0f/6.0f;
    d_M3[idx] = x;
}
__global__ void k_finishE() {
    int idx = blockIdx.x * 1024 + threadIdx.x;
    int r = idx >> 10, c = idx & 1023;
    float x = d_M0[idx] + 0.5f * d_M1[idx] + d_M4[idx];
    if (r == c) x += 1.0f;
    d_M3[idx] = x;
}

__global__ void k_Ainit() {
    int r = blockIdx.x, c = threadIdx.x;
    float v = 0.0f;
    if (r == 0 && c < 16) v = 1.0f;
    if (r == 1 && c >= 16 && c < 32) v = 1.0f;
    d_Arows[r * DD + c] = v;
}

__global__ void k_extract(float* __restrict__ out, int n) {
    int t = blockIdx.x * blockDim.x + threadIdx.x;
    if (t >= n) return;
    out[t] = 0.0f;                                    // ground state pop: exactly 0
    out[n + t]     = d_Arows[(size_t)(2 * t) * DD + 16];
    out[2 * n + t] = d_Arows[(size_t)(2 * t + 1) * DD + 16];
}

// ---------------- fp32 GEMM: C(MxDD) = A(MxDD) @ B(DDxDD) ----------------
// 64x64 tile, 256 threads (8 warps), 4x4 per thread, BK=16.
// Per-element accumulation order is strictly ascending k (numerically identical
// to the previous kernel).
#define GBK 16
__global__ void __launch_bounds__(256) sgemm256(
    int M, const float* __restrict__ A, const float* __restrict__ B, float* __restrict__ C)
{
    __shared__ float sA[GBK][64];   // transposed A tile
    __shared__ float sB[GBK][64];
    int bx = blockIdx.x, by = blockIdx.y;
    int t = threadIdx.x;
    int tx = t & 15, ty = t >> 4;
    int row0 = by * 64;

    float acc[4][4];
    #pragma unroll
    for (int i = 0; i < 4; i++)
        #pragma unroll
        for (int j = 0; j < 4; j++) acc[i][j] = 0.0f;

    for (int kt = 0; kt < DD; kt += GBK) {
        {   // stage A tile (transposed): thread t loads one float4
            int r = t >> 2, kc = t & 3;
            float4 v = make_float4(0.f, 0.f, 0.f, 0.f);
            if (row0 + r < M)
                v = *(const float4*)&A[(size_t)(row0 + r) * DD + kt + kc * 4];
            sA[kc * 4 + 0][r] = v.x;
            sA[kc * 4 + 1][r] = v.y;
            sA[kc * 4 + 2][r] = v.z;
            sA[kc * 4 + 3][r] = v.w;
        }
        {   // stage B tile
            int k = t >> 4, nc = t & 15;
            *(float4*)&sB[k][nc * 4] =
                *(const float4*)&B[(size_t)(kt + k) * DD + bx * 64 + nc * 4];
        }
        __syncthreads();
        #pragma unroll
        for (int kk = 0; kk < GBK; kk++) {
            float a[4], b[4];
            *(float4*)&a[0] = *(float4*)&sA[kk][ty * 4];
            *(float4*)&b[0] = *(float4*)&sB[kk][tx * 4];
            #pragma unroll
            for (int i = 0; i < 4; i++)
                #pragma unroll
                for (int j = 0; j < 4; j++)
                    acc[i][j] = fmaf(a[i], b[j], acc[i][j]);
        }
        __syncthreads();
    }
    #pragma unroll
    for (int i = 0; i < 4; i++) {
        int r = row0 + ty * 4 + i;
        if (r < M) {
            float4 o = make_float4(acc[i][0], acc[i][1], acc[i][2], acc[i][3]);
            *(float4*)&C[(size_t)r * DD + bx * 64 + tx * 4] = o;
        }
    }
}

// skinny GEMM for tiny M (2..32): C(MxDD) = A(MxDD) @ B(DDxDD)
// 128 threads, 8 blocks; per-column ascending-k chain; unroll 16 for MLP.
template <int MM>
__global__ void __launch_bounds__(128) sgemm_sk(
    const float* __restrict__ A, const float* __restrict__ B, float* __restrict__ C)
{
    __shared__ float sA[MM * 128];
    int c = blockIdx.x * 128 + threadIdx.x;
    float acc[MM];
    #pragma unroll
    for (int r = 0; r < MM; r++) acc[r] = 0.0f;
    for (int kt = 0; kt < DD; kt += 128) {
        for (int e = threadIdx.x; e < MM * 128; e += 128) {
            int r = e >> 7, kk = e & 127;
            sA[e] = A[(size_t)r * DD + kt + kk];
        }
        __syncthreads();
        #pragma unroll 16
        for (int kk = 0; kk < 128; kk++) {
            float bv = __ldg(&B[(size_t)(kt + kk) * DD + c]);
            #pragma unroll
            for (int r = 0; r < MM; r++)
                acc[r] = fmaf(sA[r * 128 + kk], bv, acc[r]);
        }
        __syncthreads();
    }
    #pragma unroll
    for (int r = 0; r < MM; r++) C[(size_t)r * DD + c] = acc[r];
}

// ---------------- driver ----------------
extern "C" void kernel_launch(void* const* d_in, const int* in_sizes, int n_in,
                              void* d_out, int out_size) {
    const float* log_g = (const float*)d_in[0];
    int n_steps = out_size / 3;
    if (n_steps < 1) n_steps = 1;
    if (n_steps > 1024) n_steps = 1024;

    void *p0, *p1, *p2, *p3, *p4, *pA;
    cudaGetSymbolAddress(&p0, d_M0);
    cudaGetSymbolAddress(&p1, d_M1);
    cudaGetSymbolAddress(&p2, d_M2);
    cudaGetSymbolAddress(&p3, d_M3);
    cudaGetSymbolAddress(&p4, d_M4);
    cudaGetSymbolAddress(&pA, d_Arows);
    float *M0 = (float*)p0, *M1 = (float*)p1, *M2 = (float*)p2,
          *M3 = (float*)p3, *M4 = (float*)p4, *Ar = (float*)pA;

    // Phase 0: build generator P (real basis, fp32) in M0
    k_build_H<<<1, 1024>>>(log_g);
    k_stageG<<<1024, 1024>>>();
    k_project<<<1024, 1024>>>();

    dim3 gfull(16, 16);
    // Phase 1: expm via order-6 Taylor (Paterson-Stockmeyer) + 8 squarings
    sgemm256<<<gfull, 256>>>(DD, M0, M0, M1);   // P2
    sgemm256<<<gfull, 256>>>(DD, M1, M0, M2);   // P3
    k_combineX<<<1024, 1024>>>();               // M3 = X
    sgemm256<<<gfull, 256>>>(DD, M2, M3, M4);   // T = P3 @ X
    k_finishE<<<1024, 1024>>>();                // M3 = E
    float* Ec = M3; float* Eo = M4;
    for (int s = 0; s < 8; s++) {
        sgemm256<<<gfull, 256>>>(DD, Ec, Ec, Eo);
        float* tmp = Ec; Ec = Eo; Eo = tmp;
    }
    // Ec == M3 holds U

    // Phase 2: time doubling. Arows[2a+c] = w_c U^a.
    k_Ainit<<<2, 1024>>>();
    float* Bc = Ec;
    float* scratchA = M0, *scratchB = M1;       // P, P2 dead
    int nd = 0;
    while ((1 << nd) < n_steps) nd++;
    if (nd > 10) nd = 10;
    int rows = 2;
    for (int kd = 0; kd < nd; kd++) {
        float* Adst = Ar + (size_t)rows * DD;
        switch (rows) {
            case 2:  sgemm_sk<2> <<<8, 128>>>(Ar, Bc, Adst); break;
            case 4:  sgemm_sk<4> <<<8, 128>>>(Ar, Bc, Adst); break;
            case 8:  sgemm_sk<8> <<<8, 128>>>(Ar, Bc, Adst); break;
            case 16: sgemm_sk<16><<<8, 128>>>(Ar, Bc, Adst); break;
            case 32: sgemm_sk<32><<<8, 128>>>(Ar, Bc, Adst); break;
            default:
                sgemm256<<<dim3(16, rows / 64), 256>>>(rows, Ar, Bc, Adst);
        }
        rows <<= 1;
        if (kd < nd - 1) {
            float* Bn = (Bc == scratchA) ? scratchB : scratchA;
            sgemm256<<<gfull, 256>>>(DD, Bc, Bc, Bn);
            Bc = Bn;
        }
    }

    // Phase 3: extract populations
    k_extract<<<(n_steps + 255) / 256, 256>>>((float*)d_out, n_steps);
}

// round 6
// speedup vs baseline: 163.8335x; 1.4507x over previous
#include <cuda_runtime.h>
#include <math.h>

#define DD 1024

// ---------------- static device storage (no allocation allowed) ----------------
static __device__ double d_H[32 * 32];
static __device__ double d_g;
static __device__ double d_CS[DD * DD];
static __device__ double d_CA[DD * DD];
static __device__ float  d_M0[DD * DD];     // P
static __device__ float  d_M1[DD * DD];     // P2
static __device__ float  d_M2[DD * DD];     // X
static __device__ float  d_M3[DD * DD];     // E / U ping
static __device__ float  d_M4[DD * DD];     // pong
static __device__ float  d_u[DD];           // column 16 of final power
static __device__ float  d_Arows[2048 * DD];

// ---------------- model: H on reduced 32-dim space ----------------
__device__ __forceinline__ double qmat(int r, int c) {
    if (c == r + 1) return sqrt((double)c * 0.5);
    if (r == c + 1) return sqrt((double)r * 0.5);
    return 0.0;
}

__global__ void k_build_H(const float* log_g) {
    int a = threadIdx.x;
    if (a == 0) d_g = (double)expf(log_g[0]);
    int i = a >> 5, j = a & 31;
    int si = i >> 4, vi = i & 15, v6i = vi >> 2, v10i = vi & 3;
    int sj = j >> 4, vj = j & 15, v6j = vj >> 2, v10j = vj & 3;
    const double CM2EV = 0.00012398419;
    const double E_S1 = 3.995, E_S2 = 4.9183;
    const double om6a = 596.0 * CM2EV, om10a = 919.0 * CM2EV;
    const double kap1 = -0.0964, kap2 = 0.1193;
    const double lam = 0.1825, gam = -0.018;
    double val = 0.0;
    if (si == sj) {
        if (vi == vj) val += (si == 0 ? E_S1 : E_S2) + om6a * v6i + om10a * v10i;
        if (v10i == v10j) val += (si == 0 ? kap1 : kap2) * qmat(v6i, v6j);
    } else {
        if (v6i == v6j) {
            double q2 = 0.0;
            #pragma unroll
            for (int m = 0; m < 4; m++) q2 += qmat(v10i, m) * qmat(m, v10j);
            val += lam * qmat(v10i, v10j) + gam * q2;
        }
    }
    d_H[i * 32 + j] = val;
}

// ---------------- real hermitian basis bookkeeping ----------------
__device__ __forceinline__ void decode_basis(int m, int& type, int& p, int& q) {
    if (m < 32) { type = 0; p = q = m; return; }
    int pi = (m < 528) ? (m - 32) : (m - 528);
    type = (m < 528) ? 1 : 2;
    int r = 0, cnt = 31;
    while (pi >= cnt) { pi -= cnt; r++; cnt--; }
    p = r; q = r + 1 + pi;
}

__global__ void k_stageG() {
    int n = blockIdx.x;
    int ab = threadIdx.x;
    int a = ab >> 5, b = ab & 31;
    int type, p, q;
    decode_basis(n, type, p, q);
    double v = (type == 0) ? 1.0 : 0.70710678118654752440;
    int nc = (type == 0) ? 1 : 2;
    int cc[2] = { p, q };
    int dd[2] = { q, p };
    double ww[2] = { v, (type == 2) ? -v : v };

    const double g = d_g;
    double HX = 0.0, XH = 0.0, Xab = 0.0, X16 = 0.0;
    for (int e = 0; e < nc; e++) {
        if (dd[e] == b) HX += d_H[a * 32 + cc[e]] * ww[e];
        if (cc[e] == a) XH += ww[e] * d_H[dd[e] * 32 + b];
        if (cc[e] == a && dd[e] == b) Xab += ww[e];
        if (a < 16 && b < 16 && cc[e] == a + 16 && dd[e] == b + 16) X16 += ww[e];
    }
    double diss = g * (X16 - 0.5 * Xab * (double)((a >= 16) + (b >= 16)));
    double cs, ca;
    if (type == 2) { cs = XH - HX; ca = diss; }
    else           { ca = HX - XH; cs = diss; }
    d_CS[n * DD + ab] = cs;
    d_CA[n * DD + ab] = ca;
}

__global__ void k_project() {
    int idx = blockIdx.x * 1024 + threadIdx.x;
    int m = idx >> 10, n = idx & 1023;
    int type, i, j;
    decode_basis(m, type, i, j);
    const double SQ2 = 1.41421356237309504880;
    double val;
    if (type == 0)      val = d_CS[n * DD + i * 33];
    else if (type == 1) val = SQ2 * d_CS[n * DD + i * 32 + j];
    else                val = SQ2 * d_CA[n * DD + i * 32 + j];
    const double scale = (1.0 / 0.6582119569) / 256.0;
    d_M0[m * DD + n] = (float)(val * scale);
}

__global__ void k_Ainit() {
    int r = blockIdx.x, c = threadIdx.x;
    float v = 0.0f;
    if (r == 0 && c < 16) v = 1.0f;
    if (r == 1 && c >= 16 && c < 32) v = 1.0f;
    d_Arows[r * DD + c] = v;
}

__global__ void k_extract(float* __restrict__ out, int n) {
    int t = blockIdx.x * blockDim.x + threadIdx.x;
    if (t >= n) return;
    out[t] = 0.0f;
    out[n + t]     = d_Arows[(size_t)(2 * t) * DD + 16];
    out[2 * n + t] = d_Arows[(size_t)(2 * t + 1) * DD + 16];
}

// ---------------- packed f32x2 helpers ----------------
__device__ __forceinline__ void ffma2(unsigned long long& acc,
                                      unsigned long long a, unsigned long long b) {
    asm("fma.rn.f32x2 %0, %1, %2, %0;" : "+l"(acc) : "l"(a), "l"(b));
}
__device__ __forceinline__ unsigned long long pack2(float x) {
    unsigned long long r; unsigned u = __float_as_uint(x);
    asm("mov.b64 %0, {%1, %1};" : "=l"(r) : "r"(u));
    return r;
}
__device__ __forceinline__ void unpack2(unsigned long long v, float& lo, float& hi) {
    unsigned a, b;
    asm("mov.b64 {%0, %1}, %2;" : "=r"(a), "=r"(b) : "l"(v));
    lo = __uint_as_float(a); hi = __uint_as_float(b);
}

// ---------------- GEMM tile body: C(MxDD)=A@B, 64x64 tile, 256 thr, 4x4, FFMA2 ----------------
// mode 0: C = acc
// mode 1: C = acc (=P2); X = 0.5*I + (1/6)*P + (1/24)*acc
// mode 2: C = acc + P + I     (E from T=P2@X)
#define GBK 16
__device__ __forceinline__ void gemm_tile(
    const float* __restrict__ A, const float* __restrict__ B, float* __restrict__ C,
    int M, int row0, int bx, int mode,
    const float* __restrict__ P, float* __restrict__ X)
{
    __shared__ float sA[GBK][64];
    __shared__ float sB[GBK][64];
    int t = threadIdx.x;
    int tx = t & 15, ty = t >> 4;

    unsigned long long acc[4][2];
    #pragma unroll
    for (int i = 0; i < 4; i++) { acc[i][0] = 0ULL; acc[i][1] = 0ULL; }

    for (int kt = 0; kt < DD; kt += GBK) {
        {   // stage A tile (transposed)
            int r = t >> 2, kc = t & 3;
            float4 v = make_float4(0.f, 0.f, 0.f, 0.f);
            if (row0 + r < M)
                v = *(const float4*)&A[(size_t)(row0 + r) * DD + kt + kc * 4];
            sA[kc * 4 + 0][r] = v.x;
            sA[kc * 4 + 1][r] = v.y;
            sA[kc * 4 + 2][r] = v.z;
            sA[kc * 4 + 3][r] = v.w;
        }
        {   // stage B tile
            int k = t >> 4, nc = t & 15;
            *(float4*)&sB[k][nc * 4] =
                *(const float4*)&B[(size_t)(kt + k) * DD + bx * 64 + nc * 4];
        }
        __syncthreads();
        #pragma unroll
        for (int kk = 0; kk < GBK; kk++) {
            float4 av = *(const float4*)&sA[kk][ty * 4];
            ulonglong2 bv = *(const ulonglong2*)&sB[kk][tx * 4];
            unsigned long long a0 = pack2(av.x), a1 = pack2(av.y),
                               a2 = pack2(av.z), a3 = pack2(av.w);
            ffma2(acc[0][0], a0, bv.x); ffma2(acc[0][1], a0, bv.y);
            ffma2(acc[1][0], a1, bv.x); ffma2(acc[1][1], a1, bv.y);
            ffma2(acc[2][0], a2, bv.x); ffma2(acc[2][1], a2, bv.y);
            ffma2(acc[3][0], a3, bv.x); ffma2(acc[3][1], a3, bv.y);
        }
        __syncthreads();
    }

    #pragma unroll
    for (int i = 0; i < 4; i++) {
        int r = row0 + ty * 4 + i;
        if (r >= M) continue;
        float v[4];
        unpack2(acc[i][0], v[0], v[1]);
        unpack2(acc[i][1], v[2], v[3]);
        int c0 = bx * 64 + tx * 4;
        size_t base = (size_t)r * DD + c0;
        if (mode == 0) {
            *(float4*)&C[base] = make_float4(v[0], v[1], v[2], v[3]);
        } else if (mode == 1) {
            *(float4*)&C[base] = make_float4(v[0], v[1], v[2], v[3]);
            float x[4];
            #pragma unroll
            for (int j = 0; j < 4; j++) {
                x[j] = (1.0f/6.0f) * P[base + j] + (1.0f/24.0f) * v[j];
                if (r == c0 + j) x[j] += 0.5f;
            }
            *(float4*)&X[base] = make_float4(x[0], x[1], x[2], x[3]);
        } else {  // mode 2
            float e[4];
            #pragma unroll
            for (int j = 0; j < 4; j++) {
                e[j] = v[j] + P[base + j];
                if (r == c0 + j) e[j] += 1.0f;
            }
            *(float4*)&C[base] = make_float4(e[0], e[1], e[2], e[3]);
        }
    }
}

__global__ void __launch_bounds__(256) k_gemm(
    const float* __restrict__ A, const float* __restrict__ B, float* __restrict__ C,
    int M, int mode, const float* __restrict__ P, float* __restrict__ X)
{
    gemm_tile(A, B, C, M, blockIdx.y * 64, blockIdx.x, mode, P, X);
}

// fused: blocks by<16 do Bn = Bc@Bc; by>=16 do Adst = Ar@Bc (M=rows)
__global__ void __launch_bounds__(256) k_sq_dbl(
    const float* __restrict__ Bc, float* __restrict__ Bn,
    const float* __restrict__ Ar, float* __restrict__ Adst, int rows)
{
    if (blockIdx.y < 16)
        gemm_tile(Bc, Bc, Bn, DD, blockIdx.y * 64, blockIdx.x, 0, 0, 0);
    else
        gemm_tile(Ar, Bc, Adst, rows, (blockIdx.y - 16) * 64, blockIdx.x, 0, 0, 0);
}

// grab column 16 of Bc
__global__ void k_getcol(const float* __restrict__ Bc) {
    d_u[threadIdx.x] = Bc[(size_t)threadIdx.x * DD + 16];
}

// final doubling, column 16 only: Ar[rows+r][16] = dot(Ar[r,:], u)
__global__ void __launch_bounds__(256) k_gemv(int rows) {
    __shared__ float red[256];
    int r = blockIdx.x;
    int t = threadIdx.x;
    float s = 0.0f;
    const float* row = &d_Arows[(size_t)r * DD];
    for (int k = t; k < DD; k += 256)
        s = fmaf(row[k], d_u[k], s);
    red[t] = s;
    __syncthreads();
    for (int w = 128; w > 0; w >>= 1) {
        if (t < w) red[t] += red[t + w];
        __syncthreads();
    }
    if (t == 0) d_Arows[(size_t)(rows + r) * DD + 16] = red[0];
}

// ---------------- driver ----------------
extern "C" void kernel_launch(void* const* d_in, const int* in_sizes, int n_in,
                              void* d_out, int out_size) {
    const float* log_g = (const float*)d_in[0];
    int n_steps = out_size / 3;
    if (n_steps < 1) n_steps = 1;
    if (n_steps > 1024) n_steps = 1024;

    void *p0, *p1, *p2, *p3, *p4, *pA;
    cudaGetSymbolAddress(&p0, d_M0);
    cudaGetSymbolAddress(&p1, d_M1);
    cudaGetSymbolAddress(&p2, d_M2);
    cudaGetSymbolAddress(&p3, d_M3);
    cudaGetSymbolAddress(&p4, d_M4);
    cudaGetSymbolAddress(&pA, d_Arows);
    float *M0 = (float*)p0, *M1 = (float*)p1, *M2 = (float*)p2,
          *M3 = (float*)p3, *M4 = (float*)p4, *Ar = (float*)pA;

    // Phase 0: build generator P (fp32) in M0
    k_build_H<<<1, 1024>>>(log_g);
    k_stageG<<<1024, 1024>>>();
    k_project<<<1024, 1024>>>();

    dim3 gfull(16, 16);
    // Phase 1: expm = order-4 Taylor (PS) + 8 squarings
    // P2 = P@P -> M1 ; X = 0.5I + P/6 + P2/24 -> M2
    k_gemm<<<gfull, 256>>>(M0, M0, M1, DD, 1, M0, M2);
    // E = P2@X + P + I -> M3
    k_gemm<<<gfull, 256>>>(M1, M2, M3, DD, 2, M0, 0);
    float* Ec = M3; float* Eo = M4;
    for (int s = 0; s < 8; s++) {
        k_gemm<<<gfull, 256>>>(Ec, Ec, Eo, DD, 0, 0, 0);
        float* tmp = Ec; Ec = Eo; Eo = tmp;
    }
    // Ec holds U = expm(Lsup * DT/HBAR)

    // Phase 2: time doubling (fused squaring + row-doubling)
    k_Ainit<<<2, 1024>>>();
    int nd = 0;
    while ((1 << nd) < n_steps) nd++;
    if (nd > 10) nd = 10;

    float* Bc = Ec;   // U
    float* Bn = Eo;
    int rows = 2;
    for (int kd = 0; kd + 1 < nd; kd++) {
        int dbl_tiles = (rows + 63) / 64;
        k_sq_dbl<<<dim3(16, 16 + dbl_tiles), 256>>>(
            Bc, Bn, Ar, Ar + (size_t)rows * DD, rows);
        rows <<= 1;
        float* tmp = Bc; Bc = Bn; Bn = tmp;
    }
    if (nd >= 1) {
        // final doubling: only column 16 of the new rows is ever read
        k_getcol<<<1, 1024>>>(Bc);
        k_gemv<<<rows, 256>>>(rows);
    }

    // Phase 3: extract populations
    k_extract<<<(n_steps + 255) / 256, 256>>>((float*)d_out, n_steps);
}